// round 13
// baseline (speedup 1.0000x reference)
#include <cuda_runtime.h>
#include <cuda_fp16.h>
#include <cstdint>
#include <math.h>

#define H_DIM 4096
#define E_DIM 64
#define TILE_M 64
#define KCHUNK 64
#define NCHUNKS 64
#define GAP_THRESH 2e-3f
#define CPAD 68

// cp.async pipeline: 4 stages, issue distance 2
#define STAGES 4
#define A_RSTRIDE 272              // A fp32 row stride bytes (256 data + 16 pad)
#define OFF_SB 17408               // B fp16 SW128 tile after A (64*272)
#define STAGE_BYTES 25600          // 17408 + 8192
#define DYN_SMEM (STAGES * STAGE_BYTES)   // 102400

__device__ __forceinline__ uint32_t smem_to_u32(const void* p) {
    uint32_t a;
    asm("{ .reg .u64 t; cvta.to.shared.u64 t, %1; cvt.u32.u64 %0, t; }" : "=r"(a) : "l"(p));
    return a;
}

#define CP_ASYNC16(dst, src) \
    asm volatile("cp.async.cg.shared.global [%0], [%1], 16;" :: "r"(dst), "l"(src))
#define CP_COMMIT() asm volatile("cp.async.commit_group;")
#define CP_WAIT(n) asm volatile("cp.async.wait_group %0;" :: "n"(n))

#define LDSM_X4(r0, r1, r2, r3, addr)                                          \
    asm volatile("ldmatrix.sync.aligned.m8n8.x4.shared.b16 {%0,%1,%2,%3}, [%4];" \
                 : "=r"(r0), "=r"(r1), "=r"(r2), "=r"(r3) : "r"(addr))

__device__ __forceinline__ void mma_fp16(float* c, const uint32_t* a,
                                         uint32_t b0, uint32_t b1) {
    asm volatile(
        "mma.sync.aligned.m16n8k16.row.col.f32.f16.f16.f32 "
        "{%0,%1,%2,%3}, {%4,%5,%6,%7}, {%8,%9}, {%0,%1,%2,%3};"
        : "+f"(c[0]), "+f"(c[1]), "+f"(c[2]), "+f"(c[3])
        : "r"(a[0]), "r"(a[1]), "r"(a[2]), "r"(a[3]), "r"(b0), "r"(b1));
}

__device__ __forceinline__ uint32_t h2(float a, float b) {
    __half2 t = __floats2half2_rn(a, b);
    return *(uint32_t*)&t;
}

// ---------------------------------------------------------------------------
// Globals: W as fp16 + near-tie flag list
// ---------------------------------------------------------------------------
__device__ __half g_Wh[E_DIM * H_DIM];
__device__ int g_flag_count;
__device__ int g_flag_tokens[32768];

__global__ __launch_bounds__(256) void w_half(const float* __restrict__ W) {
    if (blockIdx.x == 0 && threadIdx.x == 0) g_flag_count = 0;
    for (int i = blockIdx.x * 256 + threadIdx.x; i < E_DIM * H_DIM; i += 256 * 256)
        g_Wh[i] = __float2half_rn(W[i]);
}

// ---------------------------------------------------------------------------
// fp16 HMMA GEMM, KCHUNK=64, 64 chunks, cp.async 4-stage distance-2,
// ONE barrier per chunk. CTA: 64 tokens x 64 experts, 128 threads (4 warps).
// A staged as fp32 (fragments via LDS.64 + cvt); B staged fp16 SW128.
// ---------------------------------------------------------------------------
__global__ __launch_bounds__(128) void router_gemm_mma(const float* __restrict__ A,
                                                       float* __restrict__ C,
                                                       float* __restrict__ P,
                                                       float* __restrict__ IDX) {
    extern __shared__ __align__(16) char dsmem[];
    const uint32_t sb = smem_to_u32(dsmem);
    float* Cs = (float*)dsmem;

    const int tid = threadIdx.x;
    const int wid = tid >> 5;
    const int lane = tid & 31;
    const long tokenBase = (long)blockIdx.x * TILE_M;

    float acc[8][4];
#pragma unroll
    for (int j = 0; j < 8; j++)
#pragma unroll
        for (int i = 0; i < 4; i++) acc[j][i] = 0.0f;

    // loader mapping: thread t -> row t>>1 (0..63), half t&1
    const int lrow = tid >> 1;
    const int lhalf = tid & 1;
    const float* aG = A + (tokenBase + lrow) * H_DIM + lhalf * 32;  // 32 fp32 = 128B
    const __half* bG = g_Wh + (long)lrow * H_DIM;                   // expert row
    const uint32_t aS = sb + (uint32_t)(lrow * A_RSTRIDE + lhalf * 128);
    // B swizzled dst offsets (4 x 16B chunks per thread)
    uint32_t bSo[4];
#pragma unroll
    for (int i = 0; i < 4; i++) {
        const int ch = lhalf * 4 + i;
        bSo[i] = (uint32_t)(OFF_SB + lrow * 128 + ((ch ^ (lrow & 7)) << 4));
    }

    // A-fragment base: row = wid*16 + lane>>2, col pair = (lane&3)*2 fp32
    const uint32_t aF = (uint32_t)((wid * 16 + (lane >> 2)) * A_RSTRIDE +
                                   (lane & 3) * 8);
    const int ebase = (lane & 7) + ((lane >> 4) & 1) * 8;
    const uint32_t bhalfL = (uint32_t)((lane >> 3) & 1);

#define ISSUE(cs) do {                                                         \
        const uint32_t _so = (uint32_t)(((cs) & 3) * STAGE_BYTES);             \
        const int _kb = (cs) * KCHUNK;                                         \
        _Pragma("unroll")                                                      \
        for (int _i = 0; _i < 8; _i++)                                         \
            CP_ASYNC16(aS + _so + _i * 16, aG + _kb + _i * 4);                 \
        _Pragma("unroll")                                                      \
        for (int _i = 0; _i < 4; _i++)                                         \
            CP_ASYNC16(sb + _so + bSo[_i], bG + _kb + (lhalf * 4 + _i) * 8);   \
    } while (0)

    // prologue: chunks 0, 1
    ISSUE(0); CP_COMMIT();
    ISSUE(1); CP_COMMIT();

    for (int chunk = 0; chunk < NCHUNKS; chunk++) {
        if (chunk + 2 < NCHUNKS) ISSUE(chunk + 2);
        CP_COMMIT();
        CP_WAIT(2);            // oldest pending group (chunk) complete
        __syncthreads();       // publish cross-thread data; bounds warp skew

        const uint32_t so = (uint32_t)((chunk & 3) * STAGE_BYTES);
        const char* sA = dsmem + so;

#pragma unroll
        for (int s = 0; s < 4; s++) {
            uint32_t av[4];
            {
                const char* p0 = sA + aF + s * 64;
                float2 f0 = *(const float2*)(p0);
                float2 f1 = *(const float2*)(p0 + 8 * A_RSTRIDE);
                float2 f2 = *(const float2*)(p0 + 32);
                float2 f3 = *(const float2*)(p0 + 8 * A_RSTRIDE + 32);
                av[0] = h2(f0.x, f0.y); av[1] = h2(f1.x, f1.y);
                av[2] = h2(f2.x, f2.y); av[3] = h2(f3.x, f3.y);
            }
            uint32_t bv[16];
#pragma unroll
            for (int jt = 0; jt < 4; jt++) {
                const int erow = jt * 16 + ebase;
                const uint32_t ch = (uint32_t)(2 * s) + bhalfL;
                const uint32_t bo = (uint32_t)(erow * 128) +
                                    ((ch ^ (uint32_t)(erow & 7)) << 4);
                LDSM_X4(bv[4 * jt], bv[4 * jt + 1], bv[4 * jt + 2], bv[4 * jt + 3],
                        sb + so + OFF_SB + bo);
            }
#pragma unroll
            for (int jt = 0; jt < 4; jt++) {
                mma_fp16(acc[2 * jt], av, bv[4 * jt], bv[4 * jt + 1]);
                mma_fp16(acc[2 * jt + 1], av, bv[4 * jt + 2], bv[4 * jt + 3]);
            }
        }
    }
    __syncthreads();
#undef ISSUE

    // ---- stage logits to smem [64][CPAD] (overlays pipeline buffers) ----
    {
        const int r0 = wid * 16 + (lane >> 2);
        const int cbo = 2 * (lane & 3);
#pragma unroll
        for (int j = 0; j < 8; j++) {
            const int col = j * 8 + cbo;
            *(float2*)(Cs + r0 * CPAD + col) = make_float2(acc[j][0], acc[j][1]);
            *(float2*)(Cs + (r0 + 8) * CPAD + col) = make_float2(acc[j][2], acc[j][3]);
        }
    }
    __syncthreads();

    // ---- fused softmax + top-2 + flagging: warp w handles 16 tokens ----
#pragma unroll 1
    for (int t16 = 0; t16 < 16; t16++) {
        const int tok = wid * 16 + t16;
        const float v0 = Cs[tok * CPAD + lane];
        const float v1 = Cs[tok * CPAD + lane + 32];
        const long gtok = tokenBase + tok;

        float* crow = C + gtok * E_DIM;
        crow[lane] = v0;
        crow[lane + 32] = v1;

        float m = fmaxf(v0, v1);
#pragma unroll
        for (int o = 16; o; o >>= 1) m = fmaxf(m, __shfl_xor_sync(0xffffffffu, m, o));

        float e0 = __expf(v0 - m);
        float e1 = __expf(v1 - m);
        float s = e0 + e1;
#pragma unroll
        for (int o = 16; o; o >>= 1) s += __shfl_xor_sync(0xffffffffu, s, o);
        float inv = 1.0f / s;

        float* prow = P + gtok * E_DIM;
        prow[lane] = e0 * inv;
        prow[lane + 32] = e1 * inv;

        float bv; int bi;
        if (v0 >= v1) { bv = v0; bi = lane; } else { bv = v1; bi = lane + 32; }
#pragma unroll
        for (int o = 16; o; o >>= 1) {
            float ov = __shfl_xor_sync(0xffffffffu, bv, o);
            int   oi = __shfl_xor_sync(0xffffffffu, bi, o);
            if (ov > bv || (ov == bv && oi < bi)) { bv = ov; bi = oi; }
        }
        float c0 = (lane == bi) ? -INFINITY : v0;
        float c1 = (lane + 32 == bi) ? -INFINITY : v1;
        float sv; int si;
        if (c0 >= c1) { sv = c0; si = lane; } else { sv = c1; si = lane + 32; }
#pragma unroll
        for (int o = 16; o; o >>= 1) {
            float ov = __shfl_xor_sync(0xffffffffu, sv, o);
            int   oi = __shfl_xor_sync(0xffffffffu, si, o);
            if (ov > sv || (ov == sv && oi < si)) { sv = ov; si = oi; }
        }
        float d0 = (lane == bi || lane == si) ? -INFINITY : v0;
        float d1 = (lane + 32 == bi || lane + 32 == si) ? -INFINITY : v1;
        float tv = fmaxf(d0, d1);
#pragma unroll
        for (int o = 16; o; o >>= 1) tv = fmaxf(tv, __shfl_xor_sync(0xffffffffu, tv, o));

        if (lane == 0) {
            IDX[gtok * 2 + 0] = (float)bi;
            IDX[gtok * 2 + 1] = (float)si;
            if ((bv - sv) < GAP_THRESH || (sv - tv) < GAP_THRESH) {
                int slot = atomicAdd(&g_flag_count, 1);
                if (slot < 32768) g_flag_tokens[slot] = (int)gtok;
            }
        }
    }
}

// ---------------------------------------------------------------------------
// Refine v4: two-tier. Tier-1: plain fp32 4-acc dot (sigma ~5e-7) for every
// flagged token. Tier-2 (rare, affinity gap < 1e-5): compensated fp32
// (TwoSum + FMA error, ~1e-9) recompute. fp64 only for the 64 parallel exps.
// ---------------------------------------------------------------------------
__global__ __launch_bounds__(256) void refine_ties(const float* __restrict__ A,
                                                   const float* __restrict__ W,
                                                   float* __restrict__ IDX) {
    __shared__ float sA[H_DIM];
    __shared__ double dpart[E_DIM][4];
    __shared__ double dsum[2];
    __shared__ float fmx[2];
    __shared__ float af_s[E_DIM];
    __shared__ int s_need;

    int n = g_flag_count;
    if (n > 32768) n = 32768;

    const int t = threadIdx.x;
    const int e = t & 63;
    const int seg = t >> 6;      // 0..3

    for (int it = blockIdx.x; it < n; it += gridDim.x) {
        const int tok = g_flag_tokens[it];
        const float* arow = A + (long)tok * H_DIM;
        for (int k = t * 4; k < H_DIM; k += 1024)
            *(float4*)(sA + k) = *(const float4*)(arow + k);
        __syncthreads();

        const float* wrow = W + (long)e * H_DIM + seg * 1024;
        const float* aseg = sA + seg * 1024;

        // ---- tier 1: plain 4-acc fp32 dot ----
        {
            float a0 = 0, a1 = 0, a2 = 0, a3 = 0;
#pragma unroll 4
            for (int k = 0; k < 1024; k += 4) {
                float4 w4 = *(const float4*)(wrow + k);
                float4 a4 = *(const float4*)(aseg + k);
                a0 = __fmaf_rn(a4.x, w4.x, a0);
                a1 = __fmaf_rn(a4.y, w4.y, a1);
                a2 = __fmaf_rn(a4.z, w4.z, a2);
                a3 = __fmaf_rn(a4.w, w4.w, a3);
            }
            dpart[e][seg] = ((double)a0 + (double)a1) + ((double)a2 + (double)a3);
        }
        __syncthreads();

        // combine + softmax + top-2 decision with ambiguity check
        for (int tier = 0; tier < 2; tier++) {
            double dl = 0.0, ex = 0.0;
            if (t < 64) {
                dl = (dpart[e][0] + dpart[e][1]) + (dpart[e][2] + dpart[e][3]);
                float mv = (float)dl;
#pragma unroll
                for (int o = 16; o; o >>= 1)
                    mv = fmaxf(mv, __shfl_xor_sync(0xffffffffu, mv, o));
                if ((t & 31) == 0) fmx[t >> 5] = mv;
            }
            __syncthreads();
            if (t < 64) {
                const float m = fmaxf(fmx[0], fmx[1]);
                ex = exp(dl - (double)m);
                double sm = ex;
#pragma unroll
                for (int o = 16; o; o >>= 1)
                    sm += __shfl_xor_sync(0xffffffffu, sm, o);
                if ((t & 31) == 0) dsum[t >> 5] = sm;
            }
            __syncthreads();
            if (t < 64) af_s[e] = (float)(ex / (dsum[0] + dsum[1]));
            __syncthreads();

            if (t == 0) {
                int bi = 0;
#pragma unroll
                for (int i = 1; i < E_DIM; i++)
                    if (af_s[i] > af_s[bi]) bi = i;   // ties keep lower index
                int si = (bi == 0) ? 1 : 0;
#pragma unroll
                for (int i = 0; i < E_DIM; i++) {
                    if (i == bi || i == si) continue;
                    if (af_s[i] > af_s[si]) si = i;
                }
                float ti = -INFINITY;
#pragma unroll
                for (int i = 0; i < E_DIM; i++) {
                    if (i == bi || i == si) continue;
                    ti = fmaxf(ti, af_s[i]);
                }
                const int ambiguous = (tier == 0) &&
                    ((af_s[bi] - af_s[si] < 1e-5f) || (af_s[si] - ti < 1e-5f));
                s_need = ambiguous;
                if (!ambiguous) {
                    IDX[(long)tok * 2 + 0] = (float)bi;
                    IDX[(long)tok * 2 + 1] = (float)si;
                }
            }
            __syncthreads();
            if (!s_need) break;

            // ---- tier 2: compensated fp32 dot, then loop back to decide ----
            {
                float s = 0.0f, c = 0.0f, ce = 0.0f;
#pragma unroll 4
                for (int k = 0; k < 1024; k += 4) {
                    float4 w4 = *(const float4*)(wrow + k);
                    float4 a4 = *(const float4*)(aseg + k);
#define ACC1(av, wv) {                                   \
                    float p = __fmul_rn((av), (wv));     \
                    ce += __fmaf_rn((av), (wv), -p);     \
                    float t2 = __fadd_rn(s, p);          \
                    float z = t2 - s;                    \
                    c += (s - (t2 - z)) + (p - z);       \
                    s = t2; }
                    ACC1(a4.x, w4.x); ACC1(a4.y, w4.y);
                    ACC1(a4.z, w4.z); ACC1(a4.w, w4.w);
#undef ACC1
                }
                dpart[e][seg] = (double)s + ((double)c + (double)ce);
            }
            __syncthreads();
        }
        __syncthreads();
    }
}

// ---------------------------------------------------------------------------
// d_out: [logits T*64 | affinities T*64 | indices-as-float T*2], fp32.
// ---------------------------------------------------------------------------
extern "C" void kernel_launch(void* const* d_in, const int* in_sizes, int n_in,
                              void* d_out, int out_size) {
    const float* A = (const float*)d_in[0];
    const float* W = (const float*)d_in[1];
    const int T = in_sizes[0] / H_DIM;  // 32768

    float* out = (float*)d_out;
    float* logits = out;
    float* affin  = out + (long)T * E_DIM;
    float* idx    = out + 2L * T * E_DIM;

    cudaFuncSetAttribute(router_gemm_mma,
                         cudaFuncAttributeMaxDynamicSharedMemorySize, DYN_SMEM);

    w_half<<<256, 256>>>(W);
    router_gemm_mma<<<T / TILE_M, 128, DYN_SMEM>>>(A, logits, affin, idx);
    refine_ties<<<256, 256>>>(A, W, idx);
}

// round 14
// speedup vs baseline: 1.0431x; 1.0431x over previous
#include <cuda_runtime.h>
#include <cstdint>
#include <math.h>

#define H_DIM 4096
#define E_DIM 64
#define TILE_M 128
#define KCHUNK 32
#define NCHUNKS 128
#define GAP_THRESH 2e-3f
#define CPAD 68

// smem stage: A fp32 [128][36 words] + B tf32 [64][36 words], stride 144 B
#define RS 144
#define OFF_B 18432                 // 128*144
#define STAGE_BYTES 27648           // + 64*144
#define STAGES 4
#define DYN_SMEM (STAGES * STAGE_BYTES)   // 110592

__device__ __forceinline__ uint32_t smem_to_u32(const void* p) {
    uint32_t a;
    asm("{ .reg .u64 t; cvta.to.shared.u64 t, %1; cvt.u32.u64 %0, t; }" : "=r"(a) : "l"(p));
    return a;
}

#define CP_ASYNC16(dst, src) \
    asm volatile("cp.async.cg.shared.global [%0], [%1], 16;" :: "r"(dst), "l"(src))
#define CP_COMMIT() asm volatile("cp.async.commit_group;")
#define CP_WAIT(n) asm volatile("cp.async.wait_group %0;" :: "n"(n))

__device__ __forceinline__ uint32_t f2tf(float f) {
    uint32_t o;
    asm("cvt.rna.tf32.f32 %0, %1;" : "=r"(o) : "f"(f));
    return o;
}

__device__ __forceinline__ void mma_tf32(float* c, uint32_t a0, uint32_t a1,
                                         uint32_t a2, uint32_t a3,
                                         uint32_t b0, uint32_t b1) {
    asm volatile(
        "mma.sync.aligned.m16n8k8.row.col.f32.tf32.tf32.f32 "
        "{%0,%1,%2,%3}, {%4,%5,%6,%7}, {%8,%9}, {%0,%1,%2,%3};"
        : "+f"(c[0]), "+f"(c[1]), "+f"(c[2]), "+f"(c[3])
        : "r"(a0), "r"(a1), "r"(a2), "r"(a3), "r"(b0), "r"(b1));
}

// ---------------------------------------------------------------------------
// Globals: W pre-rounded to tf32 (stored as fp32 bits) + flag list
// ---------------------------------------------------------------------------
__device__ float g_Wtf[E_DIM * H_DIM];
__device__ int g_flag_count;
__device__ int g_flag_tokens[32768];

__global__ __launch_bounds__(256) void w_pack(const float* __restrict__ W) {
    if (blockIdx.x == 0 && threadIdx.x == 0) g_flag_count = 0;
    for (int i = blockIdx.x * 256 + threadIdx.x; i < E_DIM * H_DIM; i += 256 * 256) {
        uint32_t t = f2tf(W[i]);
        g_Wtf[i] = __uint_as_float(t);
    }
}

// ---------------------------------------------------------------------------
// TF32 single-pass GEMM (m16n8k8), cp.async 4-slot / lookahead-2.
// CTA: 128 tokens x 64 experts, 256 threads; warp w owns rows 16w..16w+15.
// Fragments via conflict-free scalar LDS (stride 144B -> bank == lane).
// ---------------------------------------------------------------------------
__global__ __launch_bounds__(256) void router_gemm_mma(const float* __restrict__ A,
                                                       float* __restrict__ C,
                                                       float* __restrict__ P,
                                                       float* __restrict__ IDX) {
    extern __shared__ __align__(16) char dsmem[];
    const uint32_t sb = smem_to_u32(dsmem);
    float* Cs = (float*)dsmem;

    const int tid = threadIdx.x;
    const int wid = tid >> 5;
    const int lane = tid & 31;
    const long tokenBase = (long)blockIdx.x * TILE_M;

    float acc[8][4];
#pragma unroll
    for (int j = 0; j < 8; j++)
#pragma unroll
        for (int i = 0; i < 4; i++) acc[j][i] = 0.0f;

    // cp.async mapping.
    // A: thread t -> row t>>1, 64B half t&1 (4 x 16B).
    const int arow = tid >> 1, ahalf = tid & 1;
    const float* aG = A + (tokenBase + arow) * H_DIM + ahalf * 16;
    const uint32_t aS = sb + (uint32_t)(arow * RS + ahalf * 64);
    // B: thread t -> expert row t>>2, 16B chunks (t&3) and (t&3)+4.
    const int brow = tid >> 2, bc = tid & 3;
    const float* bG = g_Wtf + (long)brow * H_DIM + bc * 4;
    const uint32_t bS = sb + (uint32_t)(OFF_B + brow * RS + bc * 16);

    // fragment LDS bases (bytes within stage)
    const uint32_t aF = (uint32_t)((wid * 16 + (lane >> 2)) * RS + (lane & 3) * 4);
    const uint32_t bF = (uint32_t)(OFF_B + (lane >> 2) * RS + (lane & 3) * 4);

#define ISSUE(cs) do {                                                         \
        const uint32_t _so = (uint32_t)(((cs) & 3) * STAGE_BYTES);             \
        const int _kb = (cs) * KCHUNK;                                         \
        _Pragma("unroll")                                                      \
        for (int _i = 0; _i < 4; _i++)                                         \
            CP_ASYNC16(aS + _so + _i * 16, aG + _kb + _i * 4);                 \
        CP_ASYNC16(bS + _so, bG + _kb);                                        \
        CP_ASYNC16(bS + _so + 64, bG + _kb + 16);                              \
    } while (0)

    // prologue: chunks 0, 1 (lookahead 2)
    ISSUE(0); CP_COMMIT();
    ISSUE(1); CP_COMMIT();

    for (int chunk = 0; chunk < NCHUNKS; chunk++) {
        if (chunk + 2 < NCHUNKS) ISSUE(chunk + 2);
        CP_COMMIT();
        CP_WAIT(2);            // oldest pending (chunk) complete
        __syncthreads();

        const uint32_t so = (uint32_t)((chunk & 3) * STAGE_BYTES);
        const char* sBase = dsmem + so;

#pragma unroll
        for (int ks = 0; ks < 4; ks++) {
            const uint32_t ko = (uint32_t)(ks * 32);  // 8 fp32 = 32 B
            // A fragment (m16n8k8): 4 scalar LDS + rna-round
            uint32_t a0, a1, a2, a3;
            {
                const char* p = sBase + aF + ko;
                a0 = f2tf(*(const float*)(p));
                a1 = f2tf(*(const float*)(p + 8 * RS));
                a2 = f2tf(*(const float*)(p + 16));
                a3 = f2tf(*(const float*)(p + 8 * RS + 16));
            }
#pragma unroll
            for (int nt = 0; nt < 8; nt++) {
                const char* q = sBase + bF + ko + nt * (8 * RS);
                uint32_t b0 = *(const uint32_t*)(q);
                uint32_t b1 = *(const uint32_t*)(q + 16);
                mma_tf32(acc[nt], a0, a1, a2, a3, b0, b1);
            }
        }
    }
    __syncthreads();
#undef ISSUE

    // ---- stage logits to smem [128][CPAD] (overlays pipeline buffers) ----
    {
        const int r0 = wid * 16 + (lane >> 2);
        const int cbo = 2 * (lane & 3);
#pragma unroll
        for (int j = 0; j < 8; j++) {
            const int col = j * 8 + cbo;
            *(float2*)(Cs + r0 * CPAD + col) = make_float2(acc[j][0], acc[j][1]);
            *(float2*)(Cs + (r0 + 8) * CPAD + col) = make_float2(acc[j][2], acc[j][3]);
        }
    }
    __syncthreads();

    // ---- fused softmax + top-2 + flagging: warp w handles 16 tokens ----
#pragma unroll 1
    for (int t16 = 0; t16 < 16; t16++) {
        const int tok = wid * 16 + t16;
        const float v0 = Cs[tok * CPAD + lane];
        const float v1 = Cs[tok * CPAD + lane + 32];
        const long gtok = tokenBase + tok;

        float* crow = C + gtok * E_DIM;
        crow[lane] = v0;
        crow[lane + 32] = v1;

        float m = fmaxf(v0, v1);
#pragma unroll
        for (int o = 16; o; o >>= 1) m = fmaxf(m, __shfl_xor_sync(0xffffffffu, m, o));

        float e0 = __expf(v0 - m);
        float e1 = __expf(v1 - m);
        float s = e0 + e1;
#pragma unroll
        for (int o = 16; o; o >>= 1) s += __shfl_xor_sync(0xffffffffu, s, o);
        float inv = 1.0f / s;

        float* prow = P + gtok * E_DIM;
        prow[lane] = e0 * inv;
        prow[lane + 32] = e1 * inv;

        float bv; int bi;
        if (v0 >= v1) { bv = v0; bi = lane; } else { bv = v1; bi = lane + 32; }
#pragma unroll
        for (int o = 16; o; o >>= 1) {
            float ov = __shfl_xor_sync(0xffffffffu, bv, o);
            int   oi = __shfl_xor_sync(0xffffffffu, bi, o);
            if (ov > bv || (ov == bv && oi < bi)) { bv = ov; bi = oi; }
        }
        float c0 = (lane == bi) ? -INFINITY : v0;
        float c1 = (lane + 32 == bi) ? -INFINITY : v1;
        float sv; int si;
        if (c0 >= c1) { sv = c0; si = lane; } else { sv = c1; si = lane + 32; }
#pragma unroll
        for (int o = 16; o; o >>= 1) {
            float ov = __shfl_xor_sync(0xffffffffu, sv, o);
            int   oi = __shfl_xor_sync(0xffffffffu, si, o);
            if (ov > sv || (ov == sv && oi < si)) { sv = ov; si = oi; }
        }
        float d0 = (lane == bi || lane == si) ? -INFINITY : v0;
        float d1 = (lane + 32 == bi || lane + 32 == si) ? -INFINITY : v1;
        float tv = fmaxf(d0, d1);
#pragma unroll
        for (int o = 16; o; o >>= 1) tv = fmaxf(tv, __shfl_xor_sync(0xffffffffu, tv, o));

        if (lane == 0) {
            IDX[gtok * 2 + 0] = (float)bi;
            IDX[gtok * 2 + 1] = (float)si;
            if ((bv - sv) < GAP_THRESH || (sv - tv) < GAP_THRESH) {
                int slot = atomicAdd(&g_flag_count, 1);
                if (slot < 32768) g_flag_tokens[slot] = (int)gtok;
            }
        }
    }
}

// ---------------------------------------------------------------------------
// Refine: two-tier fp64-free (validated R13 body). Tier-1 plain fp32 4-acc;
// tier-2 compensated fp32 only when affinity gaps < 1e-5.
// ---------------------------------------------------------------------------
__global__ __launch_bounds__(256) void refine_ties(const float* __restrict__ A,
                                                   const float* __restrict__ W,
                                                   float* __restrict__ IDX) {
    __shared__ float sA[H_DIM];
    __shared__ double dpart[E_DIM][4];
    __shared__ double dsum[2];
    __shared__ float fmx[2];
    __shared__ float af_s[E_DIM];
    __shared__ int s_need;

    int n = g_flag_count;
    if (n > 32768) n = 32768;

    const int t = threadIdx.x;
    const int e = t & 63;
    const int seg = t >> 6;

    for (int it = blockIdx.x; it < n; it += gridDim.x) {
        const int tok = g_flag_tokens[it];
        const float* arow = A + (long)tok * H_DIM;
        for (int k = t * 4; k < H_DIM; k += 1024)
            *(float4*)(sA + k) = *(const float4*)(arow + k);
        __syncthreads();

        const float* wrow = W + (long)e * H_DIM + seg * 1024;
        const float* aseg = sA + seg * 1024;

        {
            float a0 = 0, a1 = 0, a2 = 0, a3 = 0;
#pragma unroll 4
            for (int k = 0; k < 1024; k += 4) {
                float4 w4 = *(const float4*)(wrow + k);
                float4 a4 = *(const float4*)(aseg + k);
                a0 = __fmaf_rn(a4.x, w4.x, a0);
                a1 = __fmaf_rn(a4.y, w4.y, a1);
                a2 = __fmaf_rn(a4.z, w4.z, a2);
                a3 = __fmaf_rn(a4.w, w4.w, a3);
            }
            dpart[e][seg] = ((double)a0 + (double)a1) + ((double)a2 + (double)a3);
        }
        __syncthreads();

        for (int tier = 0; tier < 2; tier++) {
            double dl = 0.0, ex = 0.0;
            if (t < 64) {
                dl = (dpart[e][0] + dpart[e][1]) + (dpart[e][2] + dpart[e][3]);
                float mv = (float)dl;
#pragma unroll
                for (int o = 16; o; o >>= 1)
                    mv = fmaxf(mv, __shfl_xor_sync(0xffffffffu, mv, o));
                if ((t & 31) == 0) fmx[t >> 5] = mv;
            }
            __syncthreads();
            if (t < 64) {
                const float m = fmaxf(fmx[0], fmx[1]);
                ex = exp(dl - (double)m);
                double sm = ex;
#pragma unroll
                for (int o = 16; o; o >>= 1)
                    sm += __shfl_xor_sync(0xffffffffu, sm, o);
                if ((t & 31) == 0) dsum[t >> 5] = sm;
            }
            __syncthreads();
            if (t < 64) af_s[e] = (float)(ex / (dsum[0] + dsum[1]));
            __syncthreads();

            if (t == 0) {
                int bi = 0;
#pragma unroll
                for (int i = 1; i < E_DIM; i++)
                    if (af_s[i] > af_s[bi]) bi = i;
                int si = (bi == 0) ? 1 : 0;
#pragma unroll
                for (int i = 0; i < E_DIM; i++) {
                    if (i == bi || i == si) continue;
                    if (af_s[i] > af_s[si]) si = i;
                }
                float ti = -INFINITY;
#pragma unroll
                for (int i = 0; i < E_DIM; i++) {
                    if (i == bi || i == si) continue;
                    ti = fmaxf(ti, af_s[i]);
                }
                const int ambiguous = (tier == 0) &&
                    ((af_s[bi] - af_s[si] < 1e-5f) || (af_s[si] - ti < 1e-5f));
                s_need = ambiguous;
                if (!ambiguous) {
                    IDX[(long)tok * 2 + 0] = (float)bi;
                    IDX[(long)tok * 2 + 1] = (float)si;
                }
            }
            __syncthreads();
            if (!s_need) break;

            {
                float s = 0.0f, c = 0.0f, ce = 0.0f;
#pragma unroll 4
                for (int k = 0; k < 1024; k += 4) {
                    float4 w4 = *(const float4*)(wrow + k);
                    float4 a4 = *(const float4*)(aseg + k);
#define ACC1(av, wv) {                                   \
                    float p = __fmul_rn((av), (wv));     \
                    ce += __fmaf_rn((av), (wv), -p);     \
                    float t2 = __fadd_rn(s, p);          \
                    float z = t2 - s;                    \
                    c += (s - (t2 - z)) + (p - z);       \
                    s = t2; }
                    ACC1(a4.x, w4.x); ACC1(a4.y, w4.y);
                    ACC1(a4.z, w4.z); ACC1(a4.w, w4.w);
#undef ACC1
                }
                dpart[e][seg] = (double)s + ((double)c + (double)ce);
            }
            __syncthreads();
        }
        __syncthreads();
    }
}

// ---------------------------------------------------------------------------
// d_out: [logits T*64 | affinities T*64 | indices-as-float T*2], fp32.
// ---------------------------------------------------------------------------
extern "C" void kernel_launch(void* const* d_in, const int* in_sizes, int n_in,
                              void* d_out, int out_size) {
    const float* A = (const float*)d_in[0];
    const float* W = (const float*)d_in[1];
    const int T = in_sizes[0] / H_DIM;  // 32768

    float* out = (float*)d_out;
    float* logits = out;
    float* affin  = out + (long)T * E_DIM;
    float* idx    = out + 2L * T * E_DIM;

    cudaFuncSetAttribute(router_gemm_mma,
                         cudaFuncAttributeMaxDynamicSharedMemorySize, DYN_SMEM);

    w_pack<<<256, 256>>>(W);
    router_gemm_mma<<<T / TILE_M, 256, DYN_SMEM>>>(A, logits, affin, idx);
    refine_ties<<<256, 256>>>(A, W, idx);
}

// round 15
// speedup vs baseline: 1.0477x; 1.0044x over previous
#include <cuda_runtime.h>
#include <cstdint>
#include <math.h>

#define H_DIM 4096
#define E_DIM 64
#define TILE_M 128
#define KCHUNK 32
#define NCHUNKS 128
#define GAP_THRESH 2e-3f
#define CPAD 68

// smem stage: A fp32 [128][36 words] + B tf32 [64][36 words], stride 144 B
#define RS 144
#define OFF_B 18432                 // 128*144
#define STAGE_BYTES 27648           // + 64*144
#define STAGES 4
#define DYN_SMEM (STAGES * STAGE_BYTES)   // 110592

__device__ __forceinline__ uint32_t smem_to_u32(const void* p) {
    uint32_t a;
    asm("{ .reg .u64 t; cvta.to.shared.u64 t, %1; cvt.u32.u64 %0, t; }" : "=r"(a) : "l"(p));
    return a;
}

#define CP_ASYNC16(dst, src) \
    asm volatile("cp.async.cg.shared.global [%0], [%1], 16;" :: "r"(dst), "l"(src))
#define CP_COMMIT() asm volatile("cp.async.commit_group;")
#define CP_WAIT(n) asm volatile("cp.async.wait_group %0;" :: "n"(n))

__device__ __forceinline__ uint32_t f2tf(float f) {
    uint32_t o;
    asm("cvt.rna.tf32.f32 %0, %1;" : "=r"(o) : "f"(f));
    return o;
}

__device__ __forceinline__ void mma_tf32(float* c, uint32_t a0, uint32_t a1,
                                         uint32_t a2, uint32_t a3,
                                         uint32_t b0, uint32_t b1) {
    asm volatile(
        "mma.sync.aligned.m16n8k8.row.col.f32.tf32.tf32.f32 "
        "{%0,%1,%2,%3}, {%4,%5,%6,%7}, {%8,%9}, {%0,%1,%2,%3};"
        : "+f"(c[0]), "+f"(c[1]), "+f"(c[2]), "+f"(c[3])
        : "r"(a0), "r"(a1), "r"(a2), "r"(a3), "r"(b0), "r"(b1));
}

// ---------------------------------------------------------------------------
// Globals: W pre-rounded to tf32 (stored as fp32 bits) + flag list
// ---------------------------------------------------------------------------
__device__ float g_Wtf[E_DIM * H_DIM];
__device__ int g_flag_count;
__device__ int g_flag_tokens[32768];

__global__ __launch_bounds__(256) void w_pack(const float* __restrict__ W) {
    if (blockIdx.x == 0 && threadIdx.x == 0) g_flag_count = 0;
    for (int i = blockIdx.x * 256 + threadIdx.x; i < E_DIM * H_DIM; i += 256 * 256) {
        uint32_t t = f2tf(W[i]);
        g_Wtf[i] = __uint_as_float(t);
    }
}

// ---------------------------------------------------------------------------
// TF32 single-pass GEMM (m16n8k8), cp.async 4-slot / lookahead-2.
// CTA: 128 tokens x 64 experts, 256 threads; warp w owns rows 16w..16w+15.
// Fragments via conflict-free scalar LDS (stride 144B -> bank == lane).
// ---------------------------------------------------------------------------
__global__ __launch_bounds__(256) void router_gemm_mma(const float* __restrict__ A,
                                                       float* __restrict__ C,
                                                       float* __restrict__ P,
                                                       float* __restrict__ IDX) {
    extern __shared__ __align__(16) char dsmem[];
    const uint32_t sb = smem_to_u32(dsmem);
    float* Cs = (float*)dsmem;

    const int tid = threadIdx.x;
    const int wid = tid >> 5;
    const int lane = tid & 31;
    const long tokenBase = (long)blockIdx.x * TILE_M;

    float acc[8][4];
#pragma unroll
    for (int j = 0; j < 8; j++)
#pragma unroll
        for (int i = 0; i < 4; i++) acc[j][i] = 0.0f;

    // cp.async mapping.
    // A: thread t -> row t>>1, 64B half t&1 (4 x 16B).
    const int arow = tid >> 1, ahalf = tid & 1;
    const float* aG = A + (tokenBase + arow) * H_DIM + ahalf * 16;
    const uint32_t aS = sb + (uint32_t)(arow * RS + ahalf * 64);
    // B: thread t -> expert row t>>2, 16B chunks (t&3) and (t&3)+4.
    const int brow = tid >> 2, bc = tid & 3;
    const float* bG = g_Wtf + (long)brow * H_DIM + bc * 4;
    const uint32_t bS = sb + (uint32_t)(OFF_B + brow * RS + bc * 16);

    // fragment LDS bases (bytes within stage)
    const uint32_t aF = (uint32_t)((wid * 16 + (lane >> 2)) * RS + (lane & 3) * 4);
    const uint32_t bF = (uint32_t)(OFF_B + (lane >> 2) * RS + (lane & 3) * 4);

#define ISSUE(cs) do {                                                         \
        const uint32_t _so = (uint32_t)(((cs) & 3) * STAGE_BYTES);             \
        const int _kb = (cs) * KCHUNK;                                         \
        _Pragma("unroll")                                                      \
        for (int _i = 0; _i < 4; _i++)                                         \
            CP_ASYNC16(aS + _so + _i * 16, aG + _kb + _i * 4);                 \
        CP_ASYNC16(bS + _so, bG + _kb);                                        \
        CP_ASYNC16(bS + _so + 64, bG + _kb + 16);                              \
    } while (0)

    // prologue: chunks 0, 1 (lookahead 2)
    ISSUE(0); CP_COMMIT();
    ISSUE(1); CP_COMMIT();

    for (int chunk = 0; chunk < NCHUNKS; chunk++) {
        if (chunk + 2 < NCHUNKS) ISSUE(chunk + 2);
        CP_COMMIT();
        CP_WAIT(2);            // oldest pending (chunk) complete
        __syncthreads();

        const uint32_t so = (uint32_t)((chunk & 3) * STAGE_BYTES);
        const char* sBase = dsmem + so;

#pragma unroll
        for (int ks = 0; ks < 4; ks++) {
            const uint32_t ko = (uint32_t)(ks * 32);  // 8 fp32 = 32 B
            // A fragment (m16n8k8): 4 scalar LDS + rna-round
            uint32_t a0, a1, a2, a3;
            {
                const char* p = sBase + aF + ko;
                a0 = f2tf(*(const float*)(p));
                a1 = f2tf(*(const float*)(p + 8 * RS));
                a2 = f2tf(*(const float*)(p + 16));
                a3 = f2tf(*(const float*)(p + 8 * RS + 16));
            }
#pragma unroll
            for (int nt = 0; nt < 8; nt++) {
                const char* q = sBase + bF + ko + nt * (8 * RS);
                uint32_t b0 = *(const uint32_t*)(q);
                uint32_t b1 = *(const uint32_t*)(q + 16);
                mma_tf32(acc[nt], a0, a1, a2, a3, b0, b1);
            }
        }
    }
    __syncthreads();
#undef ISSUE

    // ---- stage logits to smem [128][CPAD] (overlays pipeline buffers) ----
    {
        const int r0 = wid * 16 + (lane >> 2);
        const int cbo = 2 * (lane & 3);
#pragma unroll
        for (int j = 0; j < 8; j++) {
            const int col = j * 8 + cbo;
            *(float2*)(Cs + r0 * CPAD + col) = make_float2(acc[j][0], acc[j][1]);
            *(float2*)(Cs + (r0 + 8) * CPAD + col) = make_float2(acc[j][2], acc[j][3]);
        }
    }
    __syncthreads();

    // ---- fused softmax + top-2 + flagging: warp w handles 16 tokens ----
#pragma unroll 1
    for (int t16 = 0; t16 < 16; t16++) {
        const int tok = wid * 16 + t16;
        const float v0 = Cs[tok * CPAD + lane];
        const float v1 = Cs[tok * CPAD + lane + 32];
        const long gtok = tokenBase + tok;

        float* crow = C + gtok * E_DIM;
        crow[lane] = v0;
        crow[lane + 32] = v1;

        float m = fmaxf(v0, v1);
#pragma unroll
        for (int o = 16; o; o >>= 1) m = fmaxf(m, __shfl_xor_sync(0xffffffffu, m, o));

        float e0 = __expf(v0 - m);
        float e1 = __expf(v1 - m);
        float s = e0 + e1;
#pragma unroll
        for (int o = 16; o; o >>= 1) s += __shfl_xor_sync(0xffffffffu, s, o);
        float inv = 1.0f / s;

        float* prow = P + gtok * E_DIM;
        prow[lane] = e0 * inv;
        prow[lane + 32] = e1 * inv;

        float bv; int bi;
        if (v0 >= v1) { bv = v0; bi = lane; } else { bv = v1; bi = lane + 32; }
#pragma unroll
        for (int o = 16; o; o >>= 1) {
            float ov = __shfl_xor_sync(0xffffffffu, bv, o);
            int   oi = __shfl_xor_sync(0xffffffffu, bi, o);
            if (ov > bv || (ov == bv && oi < bi)) { bv = ov; bi = oi; }
        }
        float c0 = (lane == bi) ? -INFINITY : v0;
        float c1 = (lane + 32 == bi) ? -INFINITY : v1;
        float sv; int si;
        if (c0 >= c1) { sv = c0; si = lane; } else { sv = c1; si = lane + 32; }
#pragma unroll
        for (int o = 16; o; o >>= 1) {
            float ov = __shfl_xor_sync(0xffffffffu, sv, o);
            int   oi = __shfl_xor_sync(0xffffffffu, si, o);
            if (ov > sv || (ov == sv && oi < si)) { sv = ov; si = oi; }
        }
        float d0 = (lane == bi || lane == si) ? -INFINITY : v0;
        float d1 = (lane + 32 == bi || lane + 32 == si) ? -INFINITY : v1;
        float tv = fmaxf(d0, d1);
#pragma unroll
        for (int o = 16; o; o >>= 1) tv = fmaxf(tv, __shfl_xor_sync(0xffffffffu, tv, o));

        if (lane == 0) {
            IDX[gtok * 2 + 0] = (float)bi;
            IDX[gtok * 2 + 1] = (float)si;
            if ((bv - sv) < GAP_THRESH || (sv - tv) < GAP_THRESH) {
                int slot = atomicAdd(&g_flag_count, 1);
                if (slot < 32768) g_flag_tokens[slot] = (int)gtok;
            }
        }
    }
}

// ---------------------------------------------------------------------------
// Refine: two-tier fp64-free (validated R13 body). Tier-1 plain fp32 4-acc;
// tier-2 compensated fp32 only when affinity gaps < 1e-5.
// ---------------------------------------------------------------------------
__global__ __launch_bounds__(256) void refine_ties(const float* __restrict__ A,
                                                   const float* __restrict__ W,
                                                   float* __restrict__ IDX) {
    __shared__ float sA[H_DIM];
    __shared__ double dpart[E_DIM][4];
    __shared__ double dsum[2];
    __shared__ float fmx[2];
    __shared__ float af_s[E_DIM];
    __shared__ int s_need;

    int n = g_flag_count;
    if (n > 32768) n = 32768;

    const int t = threadIdx.x;
    const int e = t & 63;
    const int seg = t >> 6;

    for (int it = blockIdx.x; it < n; it += gridDim.x) {
        const int tok = g_flag_tokens[it];
        const float* arow = A + (long)tok * H_DIM;
        for (int k = t * 4; k < H_DIM; k += 1024)
            *(float4*)(sA + k) = *(const float4*)(arow + k);
        __syncthreads();

        const float* wrow = W + (long)e * H_DIM + seg * 1024;
        const float* aseg = sA + seg * 1024;

        {
            float a0 = 0, a1 = 0, a2 = 0, a3 = 0;
#pragma unroll 4
            for (int k = 0; k < 1024; k += 4) {
                float4 w4 = *(const float4*)(wrow + k);
                float4 a4 = *(const float4*)(aseg + k);
                a0 = __fmaf_rn(a4.x, w4.x, a0);
                a1 = __fmaf_rn(a4.y, w4.y, a1);
                a2 = __fmaf_rn(a4.z, w4.z, a2);
                a3 = __fmaf_rn(a4.w, w4.w, a3);
            }
            dpart[e][seg] = ((double)a0 + (double)a1) + ((double)a2 + (double)a3);
        }
        __syncthreads();

        for (int tier = 0; tier < 2; tier++) {
            double dl = 0.0, ex = 0.0;
            if (t < 64) {
                dl = (dpart[e][0] + dpart[e][1]) + (dpart[e][2] + dpart[e][3]);
                float mv = (float)dl;
#pragma unroll
                for (int o = 16; o; o >>= 1)
                    mv = fmaxf(mv, __shfl_xor_sync(0xffffffffu, mv, o));
                if ((t & 31) == 0) fmx[t >> 5] = mv;
            }
            __syncthreads();
            if (t < 64) {
                const float m = fmaxf(fmx[0], fmx[1]);
                ex = exp(dl - (double)m);
                double sm = ex;
#pragma unroll
                for (int o = 16; o; o >>= 1)
                    sm += __shfl_xor_sync(0xffffffffu, sm, o);
                if ((t & 31) == 0) dsum[t >> 5] = sm;
            }
            __syncthreads();
            if (t < 64) af_s[e] = (float)(ex / (dsum[0] + dsum[1]));
            __syncthreads();

            if (t == 0) {
                int bi = 0;
#pragma unroll
                for (int i = 1; i < E_DIM; i++)
                    if (af_s[i] > af_s[bi]) bi = i;
                int si = (bi == 0) ? 1 : 0;
#pragma unroll
                for (int i = 0; i < E_DIM; i++) {
                    if (i == bi || i == si) continue;
                    if (af_s[i] > af_s[si]) si = i;
                }
                float ti = -INFINITY;
#pragma unroll
                for (int i = 0; i < E_DIM; i++) {
                    if (i == bi || i == si) continue;
                    ti = fmaxf(ti, af_s[i]);
                }
                const int ambiguous = (tier == 0) &&
                    ((af_s[bi] - af_s[si] < 1e-5f) || (af_s[si] - ti < 1e-5f));
                s_need = ambiguous;
                if (!ambiguous) {
                    IDX[(long)tok * 2 + 0] = (float)bi;
                    IDX[(long)tok * 2 + 1] = (float)si;
                }
            }
            __syncthreads();
            if (!s_need) break;

            {
                float s = 0.0f, c = 0.0f, ce = 0.0f;
#pragma unroll 4
                for (int k = 0; k < 1024; k += 4) {
                    float4 w4 = *(const float4*)(wrow + k);
                    float4 a4 = *(const float4*)(aseg + k);
#define ACC1(av, wv) {                                   \
                    float p = __fmul_rn((av), (wv));     \
                    ce += __fmaf_rn((av), (wv), -p);     \
                    float t2 = __fadd_rn(s, p);          \
                    float z = t2 - s;                    \
                    c += (s - (t2 - z)) + (p - z);       \
                    s = t2; }
                    ACC1(a4.x, w4.x); ACC1(a4.y, w4.y);
                    ACC1(a4.z, w4.z); ACC1(a4.w, w4.w);
#undef ACC1
                }
                dpart[e][seg] = (double)s + ((double)c + (double)ce);
            }
            __syncthreads();
        }
        __syncthreads();
    }
}

// ---------------------------------------------------------------------------
// d_out: [logits T*64 | affinities T*64 | indices-as-float T*2], fp32.
// ---------------------------------------------------------------------------
extern "C" void kernel_launch(void* const* d_in, const int* in_sizes, int n_in,
                              void* d_out, int out_size) {
    const float* A = (const float*)d_in[0];
    const float* W = (const float*)d_in[1];
    const int T = in_sizes[0] / H_DIM;  // 32768

    float* out = (float*)d_out;
    float* logits = out;
    float* affin  = out + (long)T * E_DIM;
    float* idx    = out + 2L * T * E_DIM;

    cudaFuncSetAttribute(router_gemm_mma,
                         cudaFuncAttributeMaxDynamicSharedMemorySize, DYN_SMEM);

    w_pack<<<256, 256>>>(W);
    router_gemm_mma<<<T / TILE_M, 256, DYN_SMEM>>>(A, logits, affin, idx);
    refine_ties<<<256, 256>>>(A, W, idx);
}